// round 9
// baseline (speedup 1.0000x reference)
#include <cuda_runtime.h>
#include <math_constants.h>

#define HH 1024
#define WW 1024
#define CC 128
#define NITER 8
#define TWO_RHO 89.2f         // 2 * sqrt(31.5^2 + 31.5^2) for a 64x64 region
#define FULLM 0xFFFFFFFFu
#define NBLK 256              // one CTA per 64x64 region (16x16 grid)
#define NGRP 8                // barrier arrival groups (separate L2 lines)
#define GRPSZ (NBLK / NGRP)   // 32 arrivals per group

// 4 rotating cluster position buffers (row,col interleaved).
// Invariant: g_pos[1] is all-zero at kernel entry (static init covers the
// first run; block 0 re-zeroes it at k==6 each run for the next replay).
__device__ float g_pos[4][2 * CC];
// hierarchical grid barrier: each counter on its own 128B line
__device__ __align__(128) unsigned g_grp[NGRP][32];
__device__ __align__(128) unsigned g_mst[32];
__device__ __align__(128) unsigned g_gen[32];

__device__ __forceinline__ unsigned ld_acquire_gpu(const unsigned* p) {
    unsigned v;
    asm volatile("ld.acquire.gpu.u32 %0, [%1];" : "=r"(v) : "l"(p) : "memory");
    return v;
}
__device__ __forceinline__ unsigned atom_add_acqrel(unsigned* p, unsigned a) {
    unsigned v;
    asm volatile("atom.add.acq_rel.gpu.u32 %0, [%1], %2;"
                 : "=r"(v) : "l"(p), "r"(a) : "memory");
    return v;
}
__device__ __forceinline__ void st_relaxed_gpu(unsigned* p, unsigned v) {
    asm volatile("st.relaxed.gpu.u32 [%0], %1;" :: "l"(p), "r"(v) : "memory");
}

// Two-level arrival halves per-line RMW serialization (256 -> 32+8).
// Ordering: group acq_rel add releases this CTA's work; group leader's
// relaxed reset is published by its release-add on the master; master
// leader's release-bump of gen publishes everything; pollers acquire gen.
__device__ __forceinline__ void grid_barrier(unsigned target, int gid) {
    __syncthreads();
    if (threadIdx.x == 0) {
        bool released = false;
        unsigned old = atom_add_acqrel(&g_grp[gid][0], 1u);
        if (old == GRPSZ - 1u) {
            st_relaxed_gpu(&g_grp[gid][0], 0u);
            unsigned old2 = atom_add_acqrel(&g_mst[0], 1u);
            if (old2 == NGRP - 1u) {
                st_relaxed_gpu(&g_mst[0], 0u);
                asm volatile("red.add.release.gpu.u32 [%0], %1;"
                             :: "l"(&g_gen[0]), "r"(1u) : "memory");
                released = true;
            }
        }
        if (!released) {
            unsigned g = ld_acquire_gpu(&g_gen[0]);
            int spins = 0;
            while ((int)(g - target) < 0) {
                if (++spins > 32) __nanosleep(20);  // hot-spin, then doze
                g = ld_acquire_gpu(&g_gen[0]);
            }
        }
    }
    __syncthreads();
}

// warp-wide min of a uint (nonneg float bits are order-isomorphic)
__device__ __forceinline__ unsigned warp_min_u32(unsigned v) {
    unsigned r;
    asm volatile("redux.sync.min.u32 %0, %1, 0xffffffff;" : "=r"(r) : "r"(v));
    return r;
}

__global__ void __launch_bounds__(256, 2) km_all_kernel(
    const float* __restrict__ clusters,
    const float* __restrict__ heatmap,
    float* __restrict__ out)
{
    __shared__ float2 s_cand[CC];
    __shared__ int    s_cidx[CC];
    __shared__ float  s_acc[2 * CC];
    __shared__ int    s_n;

    const int t = threadIdx.x;
    const int wid = t >> 5;
    const int lane = t & 31;
    const int gid = blockIdx.x & (NGRP - 1);
    // 64x64 region per CTA; 16 consecutive pixels per thread
    const int region_c = (blockIdx.x & 15) * 64;
    const int region_r = (blockIdx.x >> 4) * 64;
    const int row  = region_r + (t >> 2);
    const int col0 = region_c + (t & 3) * 16;
    const float frow = (float)row;
    const float fc0  = (float)col0;
    const float cy = (float)region_r + 31.5f;
    const float cx = (float)region_c + 31.5f;

    // heatmap values for this thread's 16 pixels: constant across iterations
    float h[16];
    #pragma unroll
    for (int q = 0; q < 4; ++q) {
        const float4 a = *reinterpret_cast<const float4*>(heatmap + row * WW + col0 + q * 4);
        h[q * 4 + 0] = a.x; h[q * 4 + 1] = a.y;
        h[q * 4 + 2] = a.z; h[q * 4 + 3] = a.w;
    }

    s_acc[t] = 0.0f;     // published by Phase A's __syncthreads

    // base generation (monotone across replays); every CTA reads it before any
    // bump can occur (a bump needs all NBLK arrivals, each preceded by a read)
    unsigned tgt = ld_acquire_gpu(&g_gen[0]);

    #pragma unroll 1
    for (int k = 0; k < NITER; ++k) {
        const float* cin = (k == 0) ? clusters : &g_pos[k & 3][0];
        float* cout = (k == NITER - 1) ? out : &g_pos[(k + 1) & 3][0];

        // ---- Phase A (warp 0 only): cull + O(1) zero-dup + compaction ----
        if (wid == 0) {
            const float2* cin2 = reinterpret_cast<const float2*>(cin);
            float2 c4[4];
            float  d2[4];
            float m = CUDART_INF_F;
            #pragma unroll
            for (int q = 0; q < 4; ++q) {
                // L2 load: positions were produced by global atomics
                c4[q] = __ldcg(cin2 + q * 32 + lane);
                const float dr = cy - c4[q].x, dc = cx - c4[q].y;
                d2[q] = fmaf(dr, dr, dc * dc);
                m = fminf(m, d2[q]);
            }
            const float md2 = __uint_as_float(warp_min_u32(__float_as_uint(m)));

            // first exactly-(0,0) cluster (empty clusters collapse there);
            // later (0,0) dups can never win strict-< argmin -> drop them.
            unsigned zb[4];
            #pragma unroll
            for (int q = 0; q < 4; ++q)
                zb[q] = __ballot_sync(FULLM, (c4[q].x == 0.0f) && (c4[q].y == 0.0f));
            int firstZero = 1 << 30;
            #pragma unroll
            for (int q = 3; q >= 0; --q)
                if (zb[q]) firstZero = q * 32 + (__ffs(zb[q]) - 1);

            // cluster can win argmin for some pixel in region only if
            // d(center,c) <= minD + 2*rho; margin keeps fp error conservative
            const float minD = sqrtf(md2);
            const float thr  = minD + TWO_RHO + 4.0f + 1e-5f * minD;
            const float thr2 = thr * thr;

            int base = 0;
            #pragma unroll
            for (int q = 0; q < 4; ++q) {         // ascending q keeps index order
                const int ci = q * 32 + lane;
                const bool zz = (zb[q] >> lane) & 1u;
                const bool keep = (d2[q] <= thr2) && !(zz && ci != firstZero);
                const unsigned bq = __ballot_sync(FULLM, keep);
                if (keep) {
                    const int rank = base + __popc(bq & ((1u << lane) - 1u));
                    s_cand[rank] = c4[q];
                    s_cidx[rank] = ci;
                }
                base += __popc(bq);
            }
            if (lane == 0) s_n = base;
        }
        __syncthreads();
        const int ncand = s_n;

        // ---- Phase B: 16-pixel argmin (candidates in index order) ----
        float b[16];
        int   kk[16];
        #pragma unroll
        for (int q = 0; q < 16; ++q) { b[q] = CUDART_INF_F; kk[q] = 0; }

        #pragma unroll 2
        for (int j = 0; j < ncand; ++j) {
            const float2 cl = s_cand[j];
            const float dr = frow - cl.x;
            const float dr2 = dr * dr;
            #pragma unroll
            for (int q = 0; q < 16; ++q) {
                // ordering of max(1,sqrt(d2)) == ordering of max(1,d2)
                const float dc = (fc0 + (float)q) - cl.y;
                const float d = fmaxf(fmaf(dc, dc, dr2), 1.0f);
                if (d < b[q]) { b[q] = d; kk[q] = j; }
            }
        }

        int idx[16];
        float w16[16];
        #pragma unroll
        for (int q = 0; q < 16; ++q) {
            idx[q] = s_cidx[kk[q]];
            // weight = heatmap / max(1,sqrt(d2)) = h * rsqrt(clamped d2)
            w16[q] = h[q] * rsqrtf(b[q]);
        }

        // ---- scatter: uniform-warp fast path, run-length fallback ----
        bool uni = true;
        #pragma unroll
        for (int q = 1; q < 16; ++q) uni = uni && (idx[q] == idx[0]);
        const int  u      = __shfl_sync(FULLM, idx[0], 0);
        const bool alluni = __all_sync(FULLM, uni && (idx[0] == u));

        if (alluni) {
            float wsum = 0.0f, csum = 0.0f;
            #pragma unroll
            for (int q = 0; q < 16; ++q) {
                wsum += w16[q];
                csum = fmaf(fc0 + (float)q, w16[q], csum);
            }
            float rsum = frow * wsum;
            #pragma unroll
            for (int o = 16; o; o >>= 1) {
                rsum += __shfl_xor_sync(FULLM, rsum, o);
                csum += __shfl_xor_sync(FULLM, csum, o);
            }
            if (lane == 0) {
                atomicAdd(&s_acc[2 * u],     rsum);
                atomicAdd(&s_acc[2 * u + 1], csum);
            }
        } else {
            int cur = idx[0];
            float wsum = w16[0], cwsum = fc0 * w16[0];
            #pragma unroll
            for (int q = 1; q < 16; ++q) {
                const float fcq = fc0 + (float)q;
                if (idx[q] == cur) { wsum += w16[q]; cwsum = fmaf(fcq, w16[q], cwsum); }
                else {
                    atomicAdd(&s_acc[2 * cur],     frow * wsum);
                    atomicAdd(&s_acc[2 * cur + 1], cwsum);
                    cur = idx[q]; wsum = w16[q]; cwsum = fcq * w16[q];
                }
            }
            atomicAdd(&s_acc[2 * cur],     frow * wsum);
            atomicAdd(&s_acc[2 * cur + 1], cwsum);
        }

        __syncthreads();
        // global accumulate; skip zeros (all contributions are >= +0)
        const float v = s_acc[t];
        if (v != 0.0f) atomicAdd(&cout[t], v);
        s_acc[t] = 0.0f;                  // next iter's accumulator (pre-sync'd)

        // block 0 zeroes a buffer that is idle this iteration:
        //  k<=4 : output buffer of iteration k+2
        //  k==5 : d_out (output of iteration 7)
        //  k==6 : g_pos[1] (restores entry invariant for the next replay)
        if (blockIdx.x == 0) {
            if (k <= 4)      g_pos[(k + 2) & 3][t] = 0.0f;
            else if (k == 5) out[t] = 0.0f;
            else if (k == 6) g_pos[1][t] = 0.0f;
        }

        if (k < NITER - 1) grid_barrier(++tgt, gid);
    }
}

extern "C" void kernel_launch(void* const* d_in, const int* in_sizes, int n_in,
                              void* d_out, int out_size) {
    const float* clusters = (const float*)d_in[0];
    const float* heatmap  = (const float*)d_in[1];
    if (n_in >= 2 && in_sizes[0] != 2 * CC) {
        const float* tmp = clusters; clusters = heatmap; heatmap = tmp;
    }
    km_all_kernel<<<NBLK, 256>>>(clusters, heatmap, (float*)d_out);
}